// round 4
// baseline (speedup 1.0000x reference)
#include <cuda_runtime.h>
#include <math.h>

// Per-channel parameter table (C = 192, padded to 256 channels x 64 floats).
// Layout per channel:
//  [0] flag (1.0f => affine fast path valid)
//  [1] alpha  [2] beta
//  [3..5]  W0   [6..8]  B0   [9..11] T0(=tanh t0)
//  [12..20] W1  [21..23] B1  [24..26] T1
//  [27..35] W2  [36..38] B2  [39..41] T2
//  [42..50] W3  [51..53] B3  [54..56] T3
//  [57..59] W4  [60] B4
__device__ float g_params[256][64];

__device__ __forceinline__ float softplus_f(float v) {
    // stable log1p(exp(v))
    if (v > 20.0f) return v;
    if (v < -20.0f) return expf(v);
    return log1pf(expf(v));
}

// ---------------------------------------------------------------------------
// Setup: one thread per channel. Computes softplus(weights), tanh(factors),
// verifies the affine-collapse structure, and precomputes (alpha, beta).
// ---------------------------------------------------------------------------
__global__ void eb_setup(const float* __restrict__ m0, const float* __restrict__ b0, const float* __restrict__ t0,
                         const float* __restrict__ m1, const float* __restrict__ b1, const float* __restrict__ t1,
                         const float* __restrict__ m2, const float* __restrict__ b2, const float* __restrict__ t2,
                         const float* __restrict__ m3, const float* __restrict__ b3, const float* __restrict__ t3,
                         const float* __restrict__ m4, const float* __restrict__ b4,
                         int C)
{
    int c = threadIdx.x;
    if (c >= C || c >= 256) return;
    float* P = g_params[c];

    bool affine = true;

    // layer 0: m0 (C,3,1), b0 (C,3,1), t0 (C,3,1)
    float W0[3], B0[3], T0[3];
    {
        float r0 = m0[c * 3 + 0];
        #pragma unroll
        for (int j = 0; j < 3; j++) {
            float v = m0[c * 3 + j];
            if (v != r0) affine = false;
            W0[j] = softplus_f(v);
            B0[j] = b0[c * 3 + j];
            float tv = t0[c * 3 + j];
            if (tv != 0.0f) affine = false;
            T0[j] = tanhf(tv);
        }
    }

    // layers 1..3: m (C,3,3), b (C,3,1), t (C,3,1)
    float W1[9], B1[3], T1[3], W2[9], B2[3], T2[3], W3[9], B3[3], T3[3];
    const float* ms[3] = {m1, m2, m3};
    const float* bs[3] = {b1, b2, b3};
    const float* ts[3] = {t1, t2, t3};
    float* Ws[3] = {W1, W2, W3};
    float* Bs[3] = {B1, B2, B3};
    float* Ts[3] = {T1, T2, T3};
    for (int l = 0; l < 3; l++) {
        float r0 = ms[l][c * 9 + 0];
        #pragma unroll
        for (int j = 0; j < 9; j++) {
            float v = ms[l][c * 9 + j];
            if (v != r0) affine = false;
            Ws[l][j] = softplus_f(v);
        }
        #pragma unroll
        for (int j = 0; j < 3; j++) {
            Bs[l][j] = bs[l][c * 3 + j];
            float tv = ts[l][c * 3 + j];
            if (tv != 0.0f) affine = false;
            Ts[l][j] = tanhf(tv);
        }
    }

    // layer 4: m4 (C,1,3), b4 (C,1,1)
    float W4[3], B4;
    {
        float r0 = m4[c * 3 + 0];
        #pragma unroll
        for (int j = 0; j < 3; j++) {
            float v = m4[c * 3 + j];
            if (v != r0) affine = false;
            W4[j] = softplus_f(v);
        }
        B4 = b4[c];
    }

    // alpha: slope of the collapsed affine map (valid only if matrices are
    // constant-filled and all t == 0; exact in real arithmetic then).
    float alpha = W0[0];
    alpha *= (W1[0] + W1[1] + W1[2]);
    alpha *= (W2[0] + W2[1] + W2[2]);
    alpha *= (W3[0] + W3[1] + W3[2]);
    alpha *= (W4[0] + W4[1] + W4[2]);

    // beta = F(0): forward pass with x=0 and no gating.
    float y0 = B0[0], y1 = B0[1], y2 = B0[2];
    for (int l = 0; l < 3; l++) {
        const float* W = Ws[l];
        const float* B = Bs[l];
        float z0 = W[0] * y0 + W[1] * y1 + W[2] * y2 + B[0];
        float z1 = W[3] * y0 + W[4] * y1 + W[5] * y2 + B[1];
        float z2 = W[6] * y0 + W[7] * y1 + W[8] * y2 + B[2];
        y0 = z0; y1 = z1; y2 = z2;
    }
    float beta = W4[0] * y0 + W4[1] * y1 + W4[2] * y2 + B4;

    P[0] = affine ? 1.0f : 0.0f;
    P[1] = alpha;
    P[2] = beta;
    #pragma unroll
    for (int j = 0; j < 3; j++) { P[3 + j] = W0[j]; P[6 + j] = B0[j]; P[9 + j] = T0[j]; }
    #pragma unroll
    for (int j = 0; j < 9; j++) { P[12 + j] = W1[j]; P[27 + j] = W2[j]; P[42 + j] = W3[j]; }
    #pragma unroll
    for (int j = 0; j < 3; j++) {
        P[21 + j] = B1[j]; P[24 + j] = T1[j];
        P[36 + j] = B2[j]; P[39 + j] = T2[j];
        P[51 + j] = B3[j]; P[54 + j] = T3[j];
        P[57 + j] = W4[j];
    }
    P[60] = B4;
}

// ---------------------------------------------------------------------------
// Fast path: affine collapse. Pure streaming: 1 float4 load, 2 FMA + 2 sigmoid
// per lane, 3 float4 stores. Memory-bound.
// ---------------------------------------------------------------------------
__device__ __forceinline__ float sigmoid_fast(float x) {
    float e = __expf(-x);
    return __fdividef(1.0f, 1.0f + e);
}

__global__ __launch_bounds__(256) void eb_fast(const float* __restrict__ in,
                                               float* __restrict__ out,
                                               int N, long long CN)
{
    int c = blockIdx.y;
    const float* P = g_params[c];
    if (P[0] == 0.0f) return;  // general kernel handles this channel
    float alpha = P[1];
    float beta  = P[2];

    long long base = (long long)c * N;
    int e0 = (blockIdx.x * blockDim.x + threadIdx.x) * 4;
    if (e0 >= N) return;

    float* lik = out + base;
    float* low = out + CN + base;
    float* upp = out + 2 * CN + base;

    if (e0 + 3 < N) {
        float4 x = *(const float4*)(in + base + e0);
        float4 l, u, k;
        l.x = fmaf(alpha, x.x - 0.5f, beta); u.x = fmaf(alpha, x.x + 0.5f, beta);
        l.y = fmaf(alpha, x.y - 0.5f, beta); u.y = fmaf(alpha, x.y + 0.5f, beta);
        l.z = fmaf(alpha, x.z - 0.5f, beta); u.z = fmaf(alpha, x.z + 0.5f, beta);
        l.w = fmaf(alpha, x.w - 0.5f, beta); u.w = fmaf(alpha, x.w + 0.5f, beta);
        k.x = sigmoid_fast(u.x) - sigmoid_fast(l.x);
        k.y = sigmoid_fast(u.y) - sigmoid_fast(l.y);
        k.z = sigmoid_fast(u.z) - sigmoid_fast(l.z);
        k.w = sigmoid_fast(u.w) - sigmoid_fast(l.w);
        *(float4*)(lik + e0) = k;
        *(float4*)(low + e0) = l;
        *(float4*)(upp + e0) = u;
    } else {
        for (int e = e0; e < N; e++) {
            float x = in[base + e];
            float l = fmaf(alpha, x - 0.5f, beta);
            float u = fmaf(alpha, x + 0.5f, beta);
            lik[e] = sigmoid_fast(u) - sigmoid_fast(l);
            low[e] = l;
            upp[e] = u;
        }
    }
}

// ---------------------------------------------------------------------------
// General fallback: full per-channel MLP with softplus-reparam weights and
// tanh gating. Early-exits on channels covered by the fast path.
// ---------------------------------------------------------------------------
__device__ __forceinline__ float eb_mlp(float x, const float* __restrict__ P) {
    // layer 0
    float y0 = fmaf(P[3], x, P[6]);
    float y1 = fmaf(P[4], x, P[7]);
    float y2 = fmaf(P[5], x, P[8]);
    y0 = fmaf(P[9],  tanhf(y0), y0);
    y1 = fmaf(P[10], tanhf(y1), y1);
    y2 = fmaf(P[11], tanhf(y2), y2);
    // layers 1..3
    #pragma unroll
    for (int l = 0; l < 3; l++) {
        const float* W = P + 12 + l * 15;
        const float* B = W + 9;
        const float* T = W + 12;
        float z0 = W[0] * y0 + W[1] * y1 + W[2] * y2 + B[0];
        float z1 = W[3] * y0 + W[4] * y1 + W[5] * y2 + B[1];
        float z2 = W[6] * y0 + W[7] * y1 + W[8] * y2 + B[2];
        y0 = fmaf(T[0], tanhf(z0), z0);
        y1 = fmaf(T[1], tanhf(z1), z1);
        y2 = fmaf(T[2], tanhf(z2), z2);
    }
    // layer 4
    return P[57] * y0 + P[58] * y1 + P[59] * y2 + P[60];
}

__global__ __launch_bounds__(256) void eb_general(const float* __restrict__ in,
                                                  float* __restrict__ out,
                                                  int N, long long CN)
{
    int c = blockIdx.y;
    const float* P = g_params[c];
    if (P[0] != 0.0f) return;  // fast kernel already handled this channel

    long long base = (long long)c * N;
    int e0 = (blockIdx.x * blockDim.x + threadIdx.x) * 4;
    if (e0 >= N) return;

    float* lik = out + base;
    float* low = out + CN + base;
    float* upp = out + 2 * CN + base;

    int lim = min(e0 + 4, N);
    for (int e = e0; e < lim; e++) {
        float x = in[base + e];
        float l = eb_mlp(x - 0.5f, P);
        float u = eb_mlp(x + 0.5f, P);
        float sl = 1.0f / (1.0f + expf(-l));
        float su = 1.0f / (1.0f + expf(-u));
        lik[e] = su - sl;
        low[e] = l;
        upp[e] = u;
    }
}

// ---------------------------------------------------------------------------
// Host launcher
// ---------------------------------------------------------------------------
extern "C" void kernel_launch(void* const* d_in, const int* in_sizes, int n_in,
                              void* d_out, int out_size)
{
    // Identify input ordering from sizes. The 3x3 matrices (m1,m2,m3) have
    // 1728 elements and are unambiguous markers.
    // Order A (setup_inputs dict order): inputs, m0,b0,t0, m1,b1,t1, m2,b2,t2, m3,b3,t3, m4,b4
    // Order B (reference signature):     inputs, m0,m1,m2,m3,m4, b0..b4, t0..t4
    int im[5], ib[5], it[4];
    if (n_in >= 15 && in_sizes[4] != 0 && in_sizes[7] != 0 && in_sizes[10] != 0 &&
        in_sizes[2] == in_sizes[1] /* b0 same size as m0 => interleaved */ ) {
        // Order A (interleaved)
        im[0] = 1;  ib[0] = 2;  it[0] = 3;
        im[1] = 4;  ib[1] = 5;  it[1] = 6;
        im[2] = 7;  ib[2] = 8;  it[2] = 9;
        im[3] = 10; ib[3] = 11; it[3] = 12;
        im[4] = 13; ib[4] = 14;
    } else {
        // Order B (signature)
        im[0] = 1; im[1] = 2; im[2] = 3; im[3] = 4; im[4] = 5;
        ib[0] = 6; ib[1] = 7; ib[2] = 8; ib[3] = 9; ib[4] = 10;
        it[0] = 11; it[1] = 12; it[2] = 13; it[3] = 14;
    }

    const float* in = (const float*)d_in[0];
    float* out = (float*)d_out;

    int C = in_sizes[ib[4]];            // b4 has shape (C,1,1)
    if (C <= 0 || C > 256) C = 192;     // defensive; problem uses C=192
    int N = in_sizes[0] / C;
    long long CN = (long long)C * N;

    eb_setup<<<1, 256>>>(
        (const float*)d_in[im[0]], (const float*)d_in[ib[0]], (const float*)d_in[it[0]],
        (const float*)d_in[im[1]], (const float*)d_in[ib[1]], (const float*)d_in[it[1]],
        (const float*)d_in[im[2]], (const float*)d_in[ib[2]], (const float*)d_in[it[2]],
        (const float*)d_in[im[3]], (const float*)d_in[ib[3]], (const float*)d_in[it[3]],
        (const float*)d_in[im[4]], (const float*)d_in[ib[4]],
        C);

    int n4 = (N + 3) / 4;
    dim3 grid((n4 + 255) / 256, C);
    eb_fast<<<grid, 256>>>(in, out, N, CN);
    eb_general<<<grid, 256>>>(in, out, N, CN);
}

// round 5
// speedup vs baseline: 1.0054x; 1.0054x over previous
#include <cuda_runtime.h>
#include <math.h>

// EntropyBottleneck — single fused kernel.
//
// Structure exploited (verified at runtime per channel, with full-MLP fallback):
//   * every m{i} is constant-filled  -> each layer matmul is rank-1
//   * every t{i} == 0                -> tanh gating vanishes
// => lower = alpha*(x-0.5)+beta, upper = alpha*(x+0.5)+beta per channel.
// Each block recomputes its channel's {alpha,beta} (tiny, overlapped latency),
// then pure-streams: 1 float4 load, 2 FMA + 2 fast sigmoids, 3 float4 stores.

__device__ __forceinline__ float softplus_f(float v) {
    if (v > 20.0f) return v;
    if (v < -20.0f) return expf(v);
    return log1pf(expf(v));
}

__device__ __forceinline__ float sigmoid_fast(float x) {
    float e = __expf(-x);
    return __fdividef(1.0f, 1.0f + e);
}

#define ELEMS_PER_BLOCK 2048   // 256 threads * 2 float4

__global__ __launch_bounds__(256) void eb_fused(
    const float* __restrict__ in, float* __restrict__ out,
    const float* __restrict__ m0, const float* __restrict__ b0, const float* __restrict__ t0,
    const float* __restrict__ m1, const float* __restrict__ b1, const float* __restrict__ t1,
    const float* __restrict__ m2, const float* __restrict__ b2, const float* __restrict__ t2,
    const float* __restrict__ m3, const float* __restrict__ b3, const float* __restrict__ t3,
    const float* __restrict__ m4, const float* __restrict__ b4,
    int N, long long CN)
{
    const int c   = blockIdx.y;
    const int tid = threadIdx.x;

    __shared__ float sW0[3], sB0[3], sT0[3];
    __shared__ float sW[3][9], sBv[3][3], sT[3][3];
    __shared__ float sW4[3], sB4;
    __shared__ float sAlpha, sBeta;
    __shared__ int   sFlag;

    if (tid == 0) sFlag = 1;
    __syncthreads();

    // ---- Phase 1: parallel param transform + structure verification --------
    if (tid < 3) {
        float v = m0[c * 3 + tid], r = m0[c * 3];
        if (v != r) atomicAnd(&sFlag, 0);
        sW0[tid] = softplus_f(v);
        sB0[tid] = b0[c * 3 + tid];
        float tv = t0[c * 3 + tid];
        if (tv != 0.0f) atomicAnd(&sFlag, 0);
        sT0[tid] = tanhf(tv);
    } else if (tid < 30) {
        int l = (tid - 3) / 9, j = (tid - 3) % 9;
        const float* m = (l == 0) ? m1 : (l == 1) ? m2 : m3;
        float v = m[c * 9 + j], r = m[c * 9];
        if (v != r) atomicAnd(&sFlag, 0);
        sW[l][j] = softplus_f(v);
    } else if (tid < 33) {
        int j = tid - 30;
        float v = m4[c * 3 + j], r = m4[c * 3];
        if (v != r) atomicAnd(&sFlag, 0);
        sW4[j] = softplus_f(v);
    } else if (tid < 42) {
        int l = (tid - 33) / 3, j = (tid - 33) % 3;
        const float* b = (l == 0) ? b1 : (l == 1) ? b2 : b3;
        const float* t = (l == 0) ? t1 : (l == 1) ? t2 : t3;
        sBv[l][j] = b[c * 3 + j];
        float tv = t[c * 3 + j];
        if (tv != 0.0f) atomicAnd(&sFlag, 0);
        sT[l][j] = tanhf(tv);
    } else if (tid == 42) {
        sB4 = b4[c];
    }
    __syncthreads();

    // ---- Phase 2: thread 0 folds alpha/beta --------------------------------
    if (tid == 0) {
        float alpha = sW0[0];
        alpha *= (sW[0][0] + sW[0][1] + sW[0][2]);
        alpha *= (sW[1][0] + sW[1][1] + sW[1][2]);
        alpha *= (sW[2][0] + sW[2][1] + sW[2][2]);
        alpha *= (sW4[0] + sW4[1] + sW4[2]);

        float y0 = sB0[0], y1 = sB0[1], y2 = sB0[2];
        #pragma unroll
        for (int l = 0; l < 3; l++) {
            float z0 = sW[l][0] * y0 + sW[l][1] * y1 + sW[l][2] * y2 + sBv[l][0];
            float z1 = sW[l][3] * y0 + sW[l][4] * y1 + sW[l][5] * y2 + sBv[l][1];
            float z2 = sW[l][6] * y0 + sW[l][7] * y1 + sW[l][8] * y2 + sBv[l][2];
            y0 = z0; y1 = z1; y2 = z2;
        }
        sAlpha = alpha;
        sBeta  = sW4[0] * y0 + sW4[1] * y1 + sW4[2] * y2 + sB4;
    }
    __syncthreads();

    // ---- Phase 3: stream ---------------------------------------------------
    const long long base = (long long)c * N;
    const int off = blockIdx.x * ELEMS_PER_BLOCK;
    float* lik = out + base;
    float* low = out + CN + base;
    float* upp = out + 2 * CN + base;

    if (sFlag) {
        const float alpha = sAlpha, beta = sBeta;
        #pragma unroll
        for (int i = 0; i < 2; i++) {
            int e = off + i * 1024 + tid * 4;
            if (e + 3 < N) {
                float4 x = __ldcs((const float4*)(in + base + e));
                float4 l, u, k;
                l.x = fmaf(alpha, x.x - 0.5f, beta); u.x = fmaf(alpha, x.x + 0.5f, beta);
                l.y = fmaf(alpha, x.y - 0.5f, beta); u.y = fmaf(alpha, x.y + 0.5f, beta);
                l.z = fmaf(alpha, x.z - 0.5f, beta); u.z = fmaf(alpha, x.z + 0.5f, beta);
                l.w = fmaf(alpha, x.w - 0.5f, beta); u.w = fmaf(alpha, x.w + 0.5f, beta);
                k.x = sigmoid_fast(u.x) - sigmoid_fast(l.x);
                k.y = sigmoid_fast(u.y) - sigmoid_fast(l.y);
                k.z = sigmoid_fast(u.z) - sigmoid_fast(l.z);
                k.w = sigmoid_fast(u.w) - sigmoid_fast(l.w);
                __stcs((float4*)(lik + e), k);
                __stcs((float4*)(low + e), l);
                __stcs((float4*)(upp + e), u);
            } else {
                for (int q = e; q < N; q++) {
                    float x = in[base + q];
                    float l = fmaf(alpha, x - 0.5f, beta);
                    float u = fmaf(alpha, x + 0.5f, beta);
                    lik[q] = sigmoid_fast(u) - sigmoid_fast(l);
                    low[q] = l;
                    upp[q] = u;
                }
            }
        }
    } else {
        // ---- General fallback: full per-channel MLP from smem params ------
        for (int i = 0; i < 2; i++) {
            int e0 = off + i * 1024 + tid * 4;
            int lim = min(e0 + 4, N);
            for (int e = e0; e < lim; e++) {
                float x = in[base + e];
                float r2[2];
                #pragma unroll
                for (int s = 0; s < 2; s++) {
                    float xi = x + (s ? 0.5f : -0.5f);
                    float y0 = fmaf(sW0[0], xi, sB0[0]);
                    float y1 = fmaf(sW0[1], xi, sB0[1]);
                    float y2 = fmaf(sW0[2], xi, sB0[2]);
                    y0 = fmaf(sT0[0], tanhf(y0), y0);
                    y1 = fmaf(sT0[1], tanhf(y1), y1);
                    y2 = fmaf(sT0[2], tanhf(y2), y2);
                    #pragma unroll
                    for (int l = 0; l < 3; l++) {
                        float z0 = sW[l][0] * y0 + sW[l][1] * y1 + sW[l][2] * y2 + sBv[l][0];
                        float z1 = sW[l][3] * y0 + sW[l][4] * y1 + sW[l][5] * y2 + sBv[l][1];
                        float z2 = sW[l][6] * y0 + sW[l][7] * y1 + sW[l][8] * y2 + sBv[l][2];
                        y0 = fmaf(sT[l][0], tanhf(z0), z0);
                        y1 = fmaf(sT[l][1], tanhf(z1), z1);
                        y2 = fmaf(sT[l][2], tanhf(z2), z2);
                    }
                    r2[s] = sW4[0] * y0 + sW4[1] * y1 + sW4[2] * y2 + sB4;
                }
                float sl = 1.0f / (1.0f + expf(-r2[0]));
                float su = 1.0f / (1.0f + expf(-r2[1]));
                lik[e] = su - sl;
                low[e] = r2[0];
                upp[e] = r2[1];
            }
        }
    }
}

extern "C" void kernel_launch(void* const* d_in, const int* in_sizes, int n_in,
                              void* d_out, int out_size)
{
    // Input-order detection (3x3 matrices = 1728 elems are unambiguous markers).
    // Order A (dict order): inputs, m0,b0,t0, m1,b1,t1, m2,b2,t2, m3,b3,t3, m4,b4
    // Order B (signature):  inputs, m0..m4, b0..b4, t0..t3
    int im[5], ib[5], it[4];
    if (n_in >= 15 && in_sizes[2] == in_sizes[1]) {
        im[0] = 1;  ib[0] = 2;  it[0] = 3;
        im[1] = 4;  ib[1] = 5;  it[1] = 6;
        im[2] = 7;  ib[2] = 8;  it[2] = 9;
        im[3] = 10; ib[3] = 11; it[3] = 12;
        im[4] = 13; ib[4] = 14;
    } else {
        im[0] = 1; im[1] = 2; im[2] = 3; im[3] = 4; im[4] = 5;
        ib[0] = 6; ib[1] = 7; ib[2] = 8; ib[3] = 9; ib[4] = 10;
        it[0] = 11; it[1] = 12; it[2] = 13; it[3] = 14;
    }

    const float* in = (const float*)d_in[0];
    float* out = (float*)d_out;

    int C = in_sizes[ib[4]];          // b4 is (C,1,1)
    if (C <= 0) C = 192;
    int N = in_sizes[0] / C;
    long long CN = (long long)C * N;

    dim3 grid((N + ELEMS_PER_BLOCK - 1) / ELEMS_PER_BLOCK, C);
    eb_fused<<<grid, 256>>>(
        in, out,
        (const float*)d_in[im[0]], (const float*)d_in[ib[0]], (const float*)d_in[it[0]],
        (const float*)d_in[im[1]], (const float*)d_in[ib[1]], (const float*)d_in[it[1]],
        (const float*)d_in[im[2]], (const float*)d_in[ib[2]], (const float*)d_in[it[2]],
        (const float*)d_in[im[3]], (const float*)d_in[ib[3]], (const float*)d_in[it[3]],
        (const float*)d_in[im[4]], (const float*)d_in[ib[4]],
        N, CN);
}

// round 6
// speedup vs baseline: 1.1418x; 1.1356x over previous
#include <cuda_runtime.h>
#include <math.h>

// EntropyBottleneck — 3-kernel pipeline.
// setup (parallel param fold) -> fast affine stream (low-reg) -> rare fallback.
//
// Structure exploited (verified at runtime per channel):
//   * every m{i} constant-filled -> rank-1 layers
//   * every t{i} == 0            -> tanh gating vanishes
// => lower = alpha*(x-0.5)+beta, upper = alpha*(x+0.5)+beta per channel.

// Per-channel params: [0]=flag [1]=alpha [2]=beta
// [3..5]W0 [6..8]B0 [9..11]T0 | [12..20]W1 [21..23]B1 [24..26]T1
// [27..35]W2 [36..38]B2 [39..41]T2 | [42..50]W3 [51..53]B3 [54..56]T3
// [57..59]W4 [60]B4
__device__ float g_params[256][64];

__device__ __forceinline__ float softplus_f(float v) {
    if (v > 20.0f) return v;
    if (v < -20.0f) return expf(v);
    return log1pf(expf(v));
}

__device__ __forceinline__ float sigmoid_fast(float x) {
    float e = __expf(-x);
    return __fdividef(1.0f, 1.0f + e);
}

// ---------------------------------------------------------------------------
// Setup: one block per channel, 64 threads. All softplus in parallel.
// ---------------------------------------------------------------------------
__global__ void eb_setup(
    const float* __restrict__ m0, const float* __restrict__ b0, const float* __restrict__ t0,
    const float* __restrict__ m1, const float* __restrict__ b1, const float* __restrict__ t1,
    const float* __restrict__ m2, const float* __restrict__ b2, const float* __restrict__ t2,
    const float* __restrict__ m3, const float* __restrict__ b3, const float* __restrict__ t3,
    const float* __restrict__ m4, const float* __restrict__ b4)
{
    const int c   = blockIdx.x;
    const int tid = threadIdx.x;
    float* P = g_params[c];

    __shared__ int sFlag;
    if (tid == 0) sFlag = 1;
    __syncthreads();

    if (tid < 3) {
        float v = m0[c * 3 + tid];
        if (v != m0[c * 3]) atomicAnd(&sFlag, 0);
        P[3 + tid] = softplus_f(v);
        P[6 + tid] = b0[c * 3 + tid];
        float tv = t0[c * 3 + tid];
        if (tv != 0.0f) atomicAnd(&sFlag, 0);
        P[9 + tid] = tanhf(tv);
    } else if (tid < 30) {
        int l = (tid - 3) / 9, j = (tid - 3) % 9;
        const float* m = (l == 0) ? m1 : (l == 1) ? m2 : m3;
        float v = m[c * 9 + j];
        if (v != m[c * 9]) atomicAnd(&sFlag, 0);
        P[12 + l * 15 + j] = softplus_f(v);
    } else if (tid < 33) {
        int j = tid - 30;
        float v = m4[c * 3 + j];
        if (v != m4[c * 3]) atomicAnd(&sFlag, 0);
        P[57 + j] = softplus_f(v);
    } else if (tid < 42) {
        int l = (tid - 33) / 3, j = (tid - 33) % 3;
        const float* b = (l == 0) ? b1 : (l == 1) ? b2 : b3;
        const float* t = (l == 0) ? t1 : (l == 1) ? t2 : t3;
        P[21 + l * 15 + j] = b[c * 3 + j];
        float tv = t[c * 3 + j];
        if (tv != 0.0f) atomicAnd(&sFlag, 0);
        P[24 + l * 15 + j] = tanhf(tv);
    } else if (tid == 42) {
        P[60] = b4[c];
    }
    __syncthreads();

    if (tid == 0) {
        float alpha = P[3];
        alpha *= (P[12] + P[13] + P[14]);
        alpha *= (P[27] + P[28] + P[29]);
        alpha *= (P[42] + P[43] + P[44]);
        alpha *= (P[57] + P[58] + P[59]);

        float y0 = P[6], y1 = P[7], y2 = P[8];
        #pragma unroll
        for (int l = 0; l < 3; l++) {
            const float* W = P + 12 + l * 15;
            const float* B = W + 9;
            float z0 = W[0] * y0 + W[1] * y1 + W[2] * y2 + B[0];
            float z1 = W[3] * y0 + W[4] * y1 + W[5] * y2 + B[1];
            float z2 = W[6] * y0 + W[7] * y1 + W[8] * y2 + B[2];
            y0 = z0; y1 = z1; y2 = z2;
        }
        P[1] = alpha;
        P[2] = P[57] * y0 + P[58] * y1 + P[59] * y2 + P[60];
        P[0] = sFlag ? 1.0f : 0.0f;
    }
}

// ---------------------------------------------------------------------------
// Fast path: pure streaming, low-register. 2 independent float4 per thread.
// ---------------------------------------------------------------------------
#define FAST_EPB 2048   // 256 threads * 2 float4

__global__ __launch_bounds__(256, 6) void eb_fast(
    const float* __restrict__ in, float* __restrict__ out, int N, long long CN)
{
    const int c = blockIdx.y;
    const float* P = g_params[c];
    if (__ldg(&P[0]) == 0.0f) return;
    const float alpha = __ldg(&P[1]);
    const float beta  = __ldg(&P[2]);

    const long long base = (long long)c * N;
    const int e0 = blockIdx.x * FAST_EPB + threadIdx.x * 4;
    const int e1 = e0 + 1024;

    const float* src = in + base;
    float* lik = out + base;
    float* low = out + CN + base;
    float* upp = out + 2 * CN + base;

    if (e1 + 3 < N) {
        // both loads in flight before any compute
        float4 x0 = __ldcs((const float4*)(src + e0));
        float4 x1 = __ldcs((const float4*)(src + e1));

        float4 l0, u0, k0;
        l0.x = fmaf(alpha, x0.x - 0.5f, beta); u0.x = fmaf(alpha, x0.x + 0.5f, beta);
        l0.y = fmaf(alpha, x0.y - 0.5f, beta); u0.y = fmaf(alpha, x0.y + 0.5f, beta);
        l0.z = fmaf(alpha, x0.z - 0.5f, beta); u0.z = fmaf(alpha, x0.z + 0.5f, beta);
        l0.w = fmaf(alpha, x0.w - 0.5f, beta); u0.w = fmaf(alpha, x0.w + 0.5f, beta);
        k0.x = sigmoid_fast(u0.x) - sigmoid_fast(l0.x);
        k0.y = sigmoid_fast(u0.y) - sigmoid_fast(l0.y);
        k0.z = sigmoid_fast(u0.z) - sigmoid_fast(l0.z);
        k0.w = sigmoid_fast(u0.w) - sigmoid_fast(l0.w);
        __stcs((float4*)(lik + e0), k0);
        __stcs((float4*)(low + e0), l0);
        __stcs((float4*)(upp + e0), u0);

        float4 l1, u1, k1;
        l1.x = fmaf(alpha, x1.x - 0.5f, beta); u1.x = fmaf(alpha, x1.x + 0.5f, beta);
        l1.y = fmaf(alpha, x1.y - 0.5f, beta); u1.y = fmaf(alpha, x1.y + 0.5f, beta);
        l1.z = fmaf(alpha, x1.z - 0.5f, beta); u1.z = fmaf(alpha, x1.z + 0.5f, beta);
        l1.w = fmaf(alpha, x1.w - 0.5f, beta); u1.w = fmaf(alpha, x1.w + 0.5f, beta);
        k1.x = sigmoid_fast(u1.x) - sigmoid_fast(l1.x);
        k1.y = sigmoid_fast(u1.y) - sigmoid_fast(l1.y);
        k1.z = sigmoid_fast(u1.z) - sigmoid_fast(l1.z);
        k1.w = sigmoid_fast(u1.w) - sigmoid_fast(l1.w);
        __stcs((float4*)(lik + e1), k1);
        __stcs((float4*)(low + e1), l1);
        __stcs((float4*)(upp + e1), u1);
    } else {
        #pragma unroll
        for (int i = 0; i < 2; i++) {
            int s = e0 + i * 1024;
            int lim = min(s + 4, N);
            for (int q = s; q < lim; q++) {
                float x = src[q];
                float l = fmaf(alpha, x - 0.5f, beta);
                float u = fmaf(alpha, x + 0.5f, beta);
                lik[q] = sigmoid_fast(u) - sigmoid_fast(l);
                low[q] = l;
                upp[q] = u;
            }
        }
    }
}

// ---------------------------------------------------------------------------
// General fallback: coarse sweep (32 elems/thread) — cheap no-op when unused.
// ---------------------------------------------------------------------------
#define GEN_EPB 8192    // 256 threads * 32 elems

__device__ __forceinline__ float eb_mlp(float x, const float* __restrict__ P) {
    float y0 = fmaf(P[3], x, P[6]);
    float y1 = fmaf(P[4], x, P[7]);
    float y2 = fmaf(P[5], x, P[8]);
    y0 = fmaf(P[9],  tanhf(y0), y0);
    y1 = fmaf(P[10], tanhf(y1), y1);
    y2 = fmaf(P[11], tanhf(y2), y2);
    #pragma unroll
    for (int l = 0; l < 3; l++) {
        const float* W = P + 12 + l * 15;
        const float* B = W + 9;
        const float* T = W + 12;
        float z0 = W[0] * y0 + W[1] * y1 + W[2] * y2 + B[0];
        float z1 = W[3] * y0 + W[4] * y1 + W[5] * y2 + B[1];
        float z2 = W[6] * y0 + W[7] * y1 + W[8] * y2 + B[2];
        y0 = fmaf(T[0], tanhf(z0), z0);
        y1 = fmaf(T[1], tanhf(z1), z1);
        y2 = fmaf(T[2], tanhf(z2), z2);
    }
    return P[57] * y0 + P[58] * y1 + P[59] * y2 + P[60];
}

__global__ __launch_bounds__(256) void eb_general(
    const float* __restrict__ in, float* __restrict__ out, int N, long long CN)
{
    const int c = blockIdx.y;
    if (__ldg(&g_params[c][0]) != 0.0f) return;   // fast path covered it

    __shared__ float sP[64];
    if (threadIdx.x < 64) sP[threadIdx.x] = g_params[c][threadIdx.x];
    __syncthreads();

    const long long base = (long long)c * N;
    float* lik = out + base;
    float* low = out + CN + base;
    float* upp = out + 2 * CN + base;

    const int start = blockIdx.x * GEN_EPB;
    const int end = min(start + GEN_EPB, N);
    for (int e = start + threadIdx.x; e < end; e += 256) {
        float x = in[base + e];
        float l = eb_mlp(x - 0.5f, sP);
        float u = eb_mlp(x + 0.5f, sP);
        lik[e] = 1.0f / (1.0f + expf(-u)) - 1.0f / (1.0f + expf(-l));
        low[e] = l;
        upp[e] = u;
    }
}

// ---------------------------------------------------------------------------
// Host launcher
// ---------------------------------------------------------------------------
extern "C" void kernel_launch(void* const* d_in, const int* in_sizes, int n_in,
                              void* d_out, int out_size)
{
    // Input-order detection.
    // Order A (dict order): inputs, m0,b0,t0, m1,b1,t1, m2,b2,t2, m3,b3,t3, m4,b4
    // Order B (signature):  inputs, m0..m4, b0..b4, t0..t3
    int im[5], ib[5], it[4];
    if (n_in >= 15 && in_sizes[2] == in_sizes[1]) {
        im[0] = 1;  ib[0] = 2;  it[0] = 3;
        im[1] = 4;  ib[1] = 5;  it[1] = 6;
        im[2] = 7;  ib[2] = 8;  it[2] = 9;
        im[3] = 10; ib[3] = 11; it[3] = 12;
        im[4] = 13; ib[4] = 14;
    } else {
        im[0] = 1; im[1] = 2; im[2] = 3; im[3] = 4; im[4] = 5;
        ib[0] = 6; ib[1] = 7; ib[2] = 8; ib[3] = 9; ib[4] = 10;
        it[0] = 11; it[1] = 12; it[2] = 13; it[3] = 14;
    }

    const float* in = (const float*)d_in[0];
    float* out = (float*)d_out;

    int C = in_sizes[ib[4]];          // b4 is (C,1,1)
    if (C <= 0 || C > 256) C = 192;
    int N = in_sizes[0] / C;
    long long CN = (long long)C * N;

    eb_setup<<<C, 64>>>(
        (const float*)d_in[im[0]], (const float*)d_in[ib[0]], (const float*)d_in[it[0]],
        (const float*)d_in[im[1]], (const float*)d_in[ib[1]], (const float*)d_in[it[1]],
        (const float*)d_in[im[2]], (const float*)d_in[ib[2]], (const float*)d_in[it[2]],
        (const float*)d_in[im[3]], (const float*)d_in[ib[3]], (const float*)d_in[it[3]],
        (const float*)d_in[im[4]], (const float*)d_in[ib[4]]);

    dim3 gfast((N + FAST_EPB - 1) / FAST_EPB, C);
    eb_fast<<<gfast, 256>>>(in, out, N, CN);

    dim3 ggen((N + GEN_EPB - 1) / GEN_EPB, C);
    eb_general<<<ggen, 256>>>(in, out, N, CN);
}

// round 7
// speedup vs baseline: 1.5635x; 1.3694x over previous
#include <cuda_runtime.h>
#include <math.h>

// EntropyBottleneck — 2-kernel pipeline.
//
// Structure exploited (verified at runtime per channel):
//   * every m{i} constant-filled -> rank-1 layers
//   * every t{i} == 0            -> tanh gating vanishes
// => lower = alpha*(x-0.5)+beta, upper = alpha*(x+0.5)+beta per channel.
//
// Kernel 1 (eb_prep, grid=C): computes {flag, alpha, beta} per channel via
//   shared-memory staging; if the structure does NOT hold for a channel, the
//   same kernel runs the full MLP for that channel (safety net, never taken
//   on this problem's inputs).
// Kernel 2 (eb_fast): pure stream — one float4 param load, then
//   1 ld.128 + 2 FMA + 2 fast sigmoids + 3 st.128 per 4 elems.

__device__ float4 g_ab[256];   // {flag, alpha, beta, pad} per channel

__device__ __forceinline__ float softplus_f(float v) {
    if (v > 20.0f) return v;
    if (v < -20.0f) return expf(v);
    return log1pf(expf(v));
}

__device__ __forceinline__ float sigmoid_fast(float x) {
    float e = __expf(-x);
    return __fdividef(1.0f, 1.0f + e);
}

// ---------------------------------------------------------------------------
// Prep: one block per channel, 256 threads. Shared-memory staging only.
// ---------------------------------------------------------------------------
__global__ __launch_bounds__(256) void eb_prep(
    const float* __restrict__ in, float* __restrict__ out,
    const float* __restrict__ m0, const float* __restrict__ b0, const float* __restrict__ t0,
    const float* __restrict__ m1, const float* __restrict__ b1, const float* __restrict__ t1,
    const float* __restrict__ m2, const float* __restrict__ b2, const float* __restrict__ t2,
    const float* __restrict__ m3, const float* __restrict__ b3, const float* __restrict__ t3,
    const float* __restrict__ m4, const float* __restrict__ b4,
    int N, long long CN)
{
    const int c   = blockIdx.x;
    const int tid = threadIdx.x;

    __shared__ float sW0[3], sB0[3], sT0[3];
    __shared__ float sW[3][9], sBv[3][3], sT[3][3];
    __shared__ float sW4[3], sB4;
    __shared__ int   sFlag;

    if (tid == 0) sFlag = 1;
    __syncthreads();

    if (tid < 3) {
        float v = m0[c * 3 + tid];
        if (v != m0[c * 3]) atomicAnd(&sFlag, 0);
        sW0[tid] = softplus_f(v);
        sB0[tid] = b0[c * 3 + tid];
        float tv = t0[c * 3 + tid];
        if (tv != 0.0f) atomicAnd(&sFlag, 0);
        sT0[tid] = tanhf(tv);
    } else if (tid < 30) {
        int l = (tid - 3) / 9, j = (tid - 3) % 9;
        const float* m = (l == 0) ? m1 : (l == 1) ? m2 : m3;
        float v = m[c * 9 + j];
        if (v != m[c * 9]) atomicAnd(&sFlag, 0);
        sW[l][j] = softplus_f(v);
    } else if (tid < 33) {
        int j = tid - 30;
        float v = m4[c * 3 + j];
        if (v != m4[c * 3]) atomicAnd(&sFlag, 0);
        sW4[j] = softplus_f(v);
    } else if (tid < 42) {
        int l = (tid - 33) / 3, j = (tid - 33) % 3;
        const float* b = (l == 0) ? b1 : (l == 1) ? b2 : b3;
        const float* t = (l == 0) ? t1 : (l == 1) ? t2 : t3;
        sBv[l][j] = b[c * 3 + j];
        float tv = t[c * 3 + j];
        if (tv != 0.0f) atomicAnd(&sFlag, 0);
        sT[l][j] = tanhf(tv);
    } else if (tid == 42) {
        sB4 = b4[c];
    }
    __syncthreads();

    if (tid == 0) {
        float alpha = sW0[0];
        alpha *= (sW[0][0] + sW[0][1] + sW[0][2]);
        alpha *= (sW[1][0] + sW[1][1] + sW[1][2]);
        alpha *= (sW[2][0] + sW[2][1] + sW[2][2]);
        alpha *= (sW4[0] + sW4[1] + sW4[2]);

        float y0 = sB0[0], y1 = sB0[1], y2 = sB0[2];
        #pragma unroll
        for (int l = 0; l < 3; l++) {
            float z0 = sW[l][0] * y0 + sW[l][1] * y1 + sW[l][2] * y2 + sBv[l][0];
            float z1 = sW[l][3] * y0 + sW[l][4] * y1 + sW[l][5] * y2 + sBv[l][1];
            float z2 = sW[l][6] * y0 + sW[l][7] * y1 + sW[l][8] * y2 + sBv[l][2];
            y0 = z0; y1 = z1; y2 = z2;
        }
        float beta = sW4[0] * y0 + sW4[1] * y1 + sW4[2] * y2 + sB4;
        g_ab[c] = make_float4(sFlag ? 1.0f : 0.0f, alpha, beta, 0.0f);
    }
    __syncthreads();

    if (sFlag) return;   // fast kernel handles this channel

    // ---- Safety-net fallback: full MLP for this channel (never taken on
    //      this problem's inputs; correctness preserved regardless). --------
    const long long base = (long long)c * N;
    float* lik = out + base;
    float* low = out + CN + base;
    float* upp = out + 2 * CN + base;
    for (int e = tid; e < N; e += 256) {
        float x = in[base + e];
        float r2[2];
        #pragma unroll
        for (int s = 0; s < 2; s++) {
            float xi = x + (s ? 0.5f : -0.5f);
            float y0 = fmaf(sW0[0], xi, sB0[0]);
            float y1 = fmaf(sW0[1], xi, sB0[1]);
            float y2 = fmaf(sW0[2], xi, sB0[2]);
            y0 = fmaf(sT0[0], tanhf(y0), y0);
            y1 = fmaf(sT0[1], tanhf(y1), y1);
            y2 = fmaf(sT0[2], tanhf(y2), y2);
            #pragma unroll
            for (int l = 0; l < 3; l++) {
                float z0 = sW[l][0] * y0 + sW[l][1] * y1 + sW[l][2] * y2 + sBv[l][0];
                float z1 = sW[l][3] * y0 + sW[l][4] * y1 + sW[l][5] * y2 + sBv[l][1];
                float z2 = sW[l][6] * y0 + sW[l][7] * y1 + sW[l][8] * y2 + sBv[l][2];
                y0 = fmaf(sT[l][0], tanhf(z0), z0);
                y1 = fmaf(sT[l][1], tanhf(z1), z1);
                y2 = fmaf(sT[l][2], tanhf(z2), z2);
            }
            r2[s] = sW4[0] * y0 + sW4[1] * y1 + sW4[2] * y2 + sB4;
        }
        lik[e] = 1.0f / (1.0f + expf(-r2[1])) - 1.0f / (1.0f + expf(-r2[0]));
        low[e] = r2[0];
        upp[e] = r2[1];
    }
}

// ---------------------------------------------------------------------------
// Fast path: pure streaming, low-register. 4 float4 per thread (2x2 ILP).
// ---------------------------------------------------------------------------
#define FAST_EPB 4096   // 256 threads * 4 float4

__global__ __launch_bounds__(256, 6) void eb_fast(
    const float* __restrict__ in, float* __restrict__ out, int N, long long CN)
{
    const int c = blockIdx.y;
    const float4 fab = g_ab[c];          // {flag, alpha, beta}
    if (fab.x == 0.0f) return;           // prep kernel handled this channel
    const float alpha = fab.y, beta = fab.z;

    const long long base = (long long)c * N;
    const int blk = blockIdx.x * FAST_EPB;

    const float* src = in + base;
    float* lik = out + base;
    float* low = out + CN + base;
    float* upp = out + 2 * CN + base;

    if (blk + FAST_EPB <= N) {           // block-uniform interior predicate
        #pragma unroll
        for (int i = 0; i < 2; i++) {
            const int e0 = blk + i * 2048 + threadIdx.x * 4;
            const int e1 = e0 + 1024;
            // two independent loads in flight before any compute
            float4 x0 = __ldcs((const float4*)(src + e0));
            float4 x1 = __ldcs((const float4*)(src + e1));

            float4 l0, u0, k0;
            l0.x = fmaf(alpha, x0.x - 0.5f, beta); u0.x = fmaf(alpha, x0.x + 0.5f, beta);
            l0.y = fmaf(alpha, x0.y - 0.5f, beta); u0.y = fmaf(alpha, x0.y + 0.5f, beta);
            l0.z = fmaf(alpha, x0.z - 0.5f, beta); u0.z = fmaf(alpha, x0.z + 0.5f, beta);
            l0.w = fmaf(alpha, x0.w - 0.5f, beta); u0.w = fmaf(alpha, x0.w + 0.5f, beta);
            k0.x = sigmoid_fast(u0.x) - sigmoid_fast(l0.x);
            k0.y = sigmoid_fast(u0.y) - sigmoid_fast(l0.y);
            k0.z = sigmoid_fast(u0.z) - sigmoid_fast(l0.z);
            k0.w = sigmoid_fast(u0.w) - sigmoid_fast(l0.w);
            __stcs((float4*)(lik + e0), k0);
            __stcs((float4*)(low + e0), l0);
            __stcs((float4*)(upp + e0), u0);

            float4 l1, u1, k1;
            l1.x = fmaf(alpha, x1.x - 0.5f, beta); u1.x = fmaf(alpha, x1.x + 0.5f, beta);
            l1.y = fmaf(alpha, x1.y - 0.5f, beta); u1.y = fmaf(alpha, x1.y + 0.5f, beta);
            l1.z = fmaf(alpha, x1.z - 0.5f, beta); u1.z = fmaf(alpha, x1.z + 0.5f, beta);
            l1.w = fmaf(alpha, x1.w - 0.5f, beta); u1.w = fmaf(alpha, x1.w + 0.5f, beta);
            k1.x = sigmoid_fast(u1.x) - sigmoid_fast(l1.x);
            k1.y = sigmoid_fast(u1.y) - sigmoid_fast(l1.y);
            k1.z = sigmoid_fast(u1.z) - sigmoid_fast(l1.z);
            k1.w = sigmoid_fast(u1.w) - sigmoid_fast(l1.w);
            __stcs((float4*)(lik + e1), k1);
            __stcs((float4*)(low + e1), l1);
            __stcs((float4*)(upp + e1), u1);
        }
    } else {
        #pragma unroll
        for (int i = 0; i < 4; i++) {
            int s = blk + i * 1024 + threadIdx.x * 4;
            int lim = min(s + 4, N);
            for (int q = s; q < lim; q++) {
                float x = src[q];
                float l = fmaf(alpha, x - 0.5f, beta);
                float u = fmaf(alpha, x + 0.5f, beta);
                lik[q] = sigmoid_fast(u) - sigmoid_fast(l);
                low[q] = l;
                upp[q] = u;
            }
        }
    }
}

// ---------------------------------------------------------------------------
// Host launcher
// ---------------------------------------------------------------------------
extern "C" void kernel_launch(void* const* d_in, const int* in_sizes, int n_in,
                              void* d_out, int out_size)
{
    // Input-order detection.
    // Order A (dict order): inputs, m0,b0,t0, m1,b1,t1, m2,b2,t2, m3,b3,t3, m4,b4
    // Order B (signature):  inputs, m0..m4, b0..b4, t0..t3
    int im[5], ib[5], it[4];
    if (n_in >= 15 && in_sizes[2] == in_sizes[1]) {
        im[0] = 1;  ib[0] = 2;  it[0] = 3;
        im[1] = 4;  ib[1] = 5;  it[1] = 6;
        im[2] = 7;  ib[2] = 8;  it[2] = 9;
        im[3] = 10; ib[3] = 11; it[3] = 12;
        im[4] = 13; ib[4] = 14;
    } else {
        im[0] = 1; im[1] = 2; im[2] = 3; im[3] = 4; im[4] = 5;
        ib[0] = 6; ib[1] = 7; ib[2] = 8; ib[3] = 9; ib[4] = 10;
        it[0] = 11; it[1] = 12; it[2] = 13; it[3] = 14;
    }

    const float* in = (const float*)d_in[0];
    float* out = (float*)d_out;

    int C = in_sizes[ib[4]];          // b4 is (C,1,1)
    if (C <= 0 || C > 256) C = 192;
    int N = in_sizes[0] / C;
    long long CN = (long long)C * N;

    eb_prep<<<C, 256>>>(
        in, out,
        (const float*)d_in[im[0]], (const float*)d_in[ib[0]], (const float*)d_in[it[0]],
        (const float*)d_in[im[1]], (const float*)d_in[ib[1]], (const float*)d_in[it[1]],
        (const float*)d_in[im[2]], (const float*)d_in[ib[2]], (const float*)d_in[it[2]],
        (const float*)d_in[im[3]], (const float*)d_in[ib[3]], (const float*)d_in[it[3]],
        (const float*)d_in[im[4]], (const float*)d_in[ib[4]],
        N, CN);

    dim3 gfast((N + FAST_EPB - 1) / FAST_EPB, C);
    eb_fast<<<gfast, 256>>>(in, out, N, CN);
}